// round 7
// baseline (speedup 1.0000x reference)
#include <cuda_runtime.h>
#include <math.h>

#define NN 256
#define MM 255

// Scratch (no cudaMalloc allowed)
__device__ float  g_gp[8][NN * NN];   // partial Gram per 32-dim chunk
__device__ float  g_nrm[NN];          // squared norms of stacked rows
__device__ double g_acc;

__device__ __forceinline__ float tanha(float x) {
    float y;
    asm("tanh.approx.f32 %0, %1;" : "=f"(y) : "f"(x));
    return y;
}

// ---------------------------------------------------------------------------
// Kernel 1: blocks 0..511: partial Gram G_ij over 32-dim chunks (32x32 tile,
// 2x2 register tiling, K-major smem). Block 512: squared norms from features
// (overlaps with the Gram blocks; avoids uncoalesced diag reads later).
// ---------------------------------------------------------------------------
__global__ void gram_kernel(const float* __restrict__ features) {
    __shared__ float As[32 * 34];
    __shared__ float Bs[32 * 34];

    const int bid = blockIdx.x;
    const int tid = threadIdx.x;

    if (bid == 512) {                       // norms block
        const int w = tid >> 5, lane = tid & 31;
        for (int r = w; r < NN; r += 8) {
            const float4* row = (const float4*)(features + ((((r & 127) << 1) + (r >> 7)) << 8));
            const float4 a = row[lane];
            const float4 b = row[lane + 32];
            float s = a.x * a.x + a.y * a.y + a.z * a.z + a.w * a.w
                    + b.x * b.x + b.y * b.y + b.z * b.z + b.w * b.w;
#pragma unroll
            for (int o = 16; o; o >>= 1) s += __shfl_xor_sync(0xFFFFFFFFu, s, o);
            if (lane == 0) g_nrm[r] = s;
        }
        return;
    }

    const int jt  = (bid & 7) << 5;
    const int it  = ((bid >> 3) & 7) << 5;
    const int ch  = bid >> 6;               // 0..7

    if (bid == 0 && tid == 0) g_acc = 0.0;

    {   // load 32 rows x 32 dims, transpose into K-major smem
        const int r   = tid >> 3;
        const int c4  = tid & 7;
        const int col = (ch << 5) + (c4 << 2);
        const int gi  = it + r;
        const int gj  = jt + r;
        const float4 a = *(const float4*)&features[(((gi & 127) << 1) + (gi >> 7)) * 256 + col];
        const float4 b = *(const float4*)&features[(((gj & 127) << 1) + (gj >> 7)) * 256 + col];
        const int k0 = c4 << 2;
        As[(k0 + 0) * 34 + r] = a.x;  As[(k0 + 1) * 34 + r] = a.y;
        As[(k0 + 2) * 34 + r] = a.z;  As[(k0 + 3) * 34 + r] = a.w;
        Bs[(k0 + 0) * 34 + r] = b.x;  Bs[(k0 + 1) * 34 + r] = b.y;
        Bs[(k0 + 2) * 34 + r] = b.z;  Bs[(k0 + 3) * 34 + r] = b.w;
    }
    __syncthreads();

    const int ty = tid >> 4;
    const int tx = tid & 15;
    float a00 = 0, a01 = 0, a10 = 0, a11 = 0;
#pragma unroll
    for (int k = 0; k < 32; k++) {
        const float2 a = *(const float2*)&As[k * 34 + (ty << 1)];
        const float2 b = *(const float2*)&Bs[k * 34 + (tx << 1)];
        a00 = fmaf(a.x, b.x, a00);
        a01 = fmaf(a.x, b.y, a01);
        a10 = fmaf(a.y, b.x, a10);
        a11 = fmaf(a.y, b.y, a11);
    }
    const int r0 = it + (ty << 1);
    const int c0 = jt + (tx << 1);
    *(float2*)&g_gp[ch][r0 * NN + c0]       = make_float2(a00, a01);
    *(float2*)&g_gp[ch][(r0 + 1) * NN + c0] = make_float2(a10, a11);
}

// ---------------------------------------------------------------------------
// Kernel 2: 256 blocks (one per row i) x 256 threads.
// Prologue (1 j per thread, all-coalesced loads): z from Gram + norms;
// stable ranks via match_any; records permuted into [+ by lad | - by lad | 0]
// segments. Main loop per permuted k: THREE UNIFORM-BOUND loops over all
// segments (no skips; eq-run neg terms added like everything else), then a
// tiny divergent fixup that SUBTRACTS the eq-run neg terms (recomputed
// bit-identically) and adds the pos terms. j==k cancels the same way; its
// exact neg value 1 is the accumulator init.
//   + seg:  emd = E_j*e^{zk},  tn = tanh(q_j - ckP), ckP = rhk - zk/2
//   - seg:  emd = E_j*e^{-zk}, tn = tanh(q_j - ckM), ckM = rhk + zk/2
//   0 seg:  neg += 1 + tanh(q_j - rhk)            (q_j = rh_j, d == 0)
//   pos:    ad = |u_j -+ zk|; pos += ad*(1 + tanh(ad/2 - 0.05))
// ---------------------------------------------------------------------------
__global__ void main_kernel(const int* __restrict__ labels) {
    __shared__ float2 sEQ[NN];     // permuted {E_j, q_j = rh_j - u_j/2}
    __shared__ float4 sKR[NN];     // permuted {z, rh, ladf, 0}
    __shared__ float  sU[NN];      // permuted u_j
    __shared__ int    cntL[8][16], cntK[8][32];
    __shared__ int    sumL[16], sumK[32];
    __shared__ int    histBase[16];
    __shared__ int    BP[10], CP[10], BM[10], CM[10];
    __shared__ int    sNP, sNE;
    __shared__ float  red[256];

    const int i    = blockIdx.x;
    const int tid  = threadIdx.x;
    const int lane = tid & 31;
    const int wid  = tid >> 5;
    const unsigned lt = (1u << lane) - 1u;
    const int li   = labels[i & 127];

    cntK[wid][lane] = 0;
    if (tid < 128) cntL[tid >> 4][tid & 15] = 0;
    __syncthreads();

    // ---- phase 1: per-j basics (j = tid), all loads coalesced ----
    float z = 0.0f, sgn = 0.0f;
    int lad = 15, key = 31;
    if (tid < MM) {
        const int c = tid + (tid >= i);
        float gij = 0.0f;
#pragma unroll
        for (int ch = 0; ch < 8; ch++) gij += g_gp[ch][i * NN + c];
        z = sqrtf(fmaxf(fmaf(-2.0f, gij, g_nrm[i] + g_nrm[c]), 0.0f));
        const int ld = li - labels[c & 127];
        lad = ld < 0 ? -ld : ld;
        key = (lad == 0) ? 0 : (ld > 0 ? lad : 16 + lad);
        sgn = (float)((ld > 0) - (ld < 0));
    }
    const unsigned mL = __match_any_sync(0xFFFFFFFFu, lad);
    const unsigned mK = __match_any_sync(0xFFFFFFFFu, key);
    const int tieL = __popc(mL & lt);
    const int tieK = __popc(mK & lt);
    cntL[wid][lad & 15] = __popc(mL);
    cntK[wid][key]      = __popc(mK);
    __syncthreads();

    if (tid < 16) { int s = 0;
#pragma unroll
        for (int g = 0; g < 8; g++) s += cntL[g][tid];
        sumL[tid] = s; }
    if (tid >= 32 && tid < 64) { int s = 0; const int b = tid - 32;
#pragma unroll
        for (int g = 0; g < 8; g++) s += cntK[g][b];
        sumK[b] = s; }
    __syncthreads();

    if (tid == 0) {
        int run = 0;
#pragma unroll
        for (int b = 0; b < 16; b++) { histBase[b] = run; run += sumL[b]; }
        run = 0;
#pragma unroll
        for (int b = 1; b <= 9; b++) { BP[b] = run; CP[b] = sumK[b]; run += sumK[b]; }
        sNP = run;
#pragma unroll
        for (int b = 1; b <= 9; b++) { BM[b] = run; CM[b] = sumK[16 + b]; run += sumK[16 + b]; }
        sNE = run;
        BP[0] = 0; CP[0] = 0; BM[0] = sNP; CM[0] = 0;
    }
    __syncthreads();

    // ---- phase 2: ranks + deterministic placement ----
    if (tid < MM) {
        int tl = tieL, tk = tieK;
        for (int gg = 0; gg < wid; gg++) { tl += cntL[gg][lad]; tk += cntK[gg][key]; }
        const int rank = histBase[lad] + tl;
        const float rh = 5.0f * (float)rank;     // (rank/delta)/2
        int place;
        if (key == 0)       place = sNE + tk;
        else if (key < 16)  place = BP[key] + tk;
        else                place = BM[key - 16] + tk;
        const float u = sgn * z;
        const float E = __expf(-u);
        sEQ[place] = make_float2(E, fmaf(-0.5f, u, rh));
        sKR[place] = make_float4(z, rh, (float)lad, 0.0f);
        sU[place]  = u;
    }
    __syncthreads();

    // ---- main loop: thread handles permuted k position p = tid ----
    float term = 0.0f;
    if (tid < MM) {
        const float4 kr = sKR[tid];
        const float zk  = kr.x;
        const float rhk = kr.y;
        const int ladk  = (int)kr.z;
        const float epk = __expf(zk);
        const float enk = __expf(-zk);
        const float ckP = fmaf(-0.5f, zk, rhk);
        const float ckM = fmaf( 0.5f, zk, rhk);
        const int NP = sNP, NE = sNE;

        float neg = 1.0f;                   // exact j==k contribution
        float pos = 0.0f;

#pragma unroll 4
        for (int j = 0; j < NP; j++) {      // + segment (uniform bounds)
            const float2 t = sEQ[j];
            const float emd = t.x * epk;
            const float tn  = tanha(t.y - ckP);
            neg += fmaf(emd, tn, emd);
        }
#pragma unroll 4
        for (int j = NP; j < NE; j++) {     // - segment (uniform bounds)
            const float2 t = sEQ[j];
            const float emd = t.x * enk;
            const float tn  = tanha(t.y - ckM);
            neg += fmaf(emd, tn, emd);
        }
#pragma unroll 4
        for (int j = NE; j < MM; j++) {     // zero segment (uniform bounds)
            const float tn = tanha(sEQ[j].y - rhk);
            neg += 1.0f + tn;
        }

        // ---- fixup: subtract eq-run neg terms (bit-identical), add pos ----
        if (ladk != 0) {
            const int loP = BP[ladk], hiP = loP + CP[ladk];
            for (int j = loP; j < hiP; j++) {
                const float2 t = sEQ[j];
                const float emd = t.x * epk;
                const float tn  = tanha(t.y - ckP);
                neg -= fmaf(emd, tn, emd);
                const float d  = sU[j] - zk;
                const float ad = fabsf(d);
                pos += fmaf(ad, tanha(fmaf(0.5f, ad, -0.05f)), ad);
            }
            const int loM = BM[ladk], hiM = loM + CM[ladk];
            for (int j = loM; j < hiM; j++) {
                const float2 t = sEQ[j];
                const float emd = t.x * enk;
                const float tn  = tanha(t.y - ckM);
                neg -= fmaf(emd, tn, emd);
                const float d  = sU[j] + zk;
                const float ad = fabsf(d);
                pos += fmaf(ad, tanha(fmaf(0.5f, ad, -0.05f)), ad);
            }
        } else {
            for (int j = NE; j < MM; j++) { // zero-seg pairs are pos (== 0)
                const float tn = tanha(sEQ[j].y - rhk);
                neg -= 1.0f + tn;           // includes j==k's exact 1; init restores it
            }
        }
        term = pos + logf(neg);
    }
    red[tid] = term;
    __syncthreads();
#pragma unroll
    for (int s = 128; s > 0; s >>= 1) {
        if (tid < s) red[tid] += red[tid + s];
        __syncthreads();
    }
    if (tid == 0) atomicAdd(&g_acc, (double)red[0]);
}

__global__ void fin_kernel(float* __restrict__ out) {
    out[0] = (float)(g_acc / (double)(NN * MM));
}

extern "C" void kernel_launch(void* const* d_in, const int* in_sizes, int n_in,
                              void* d_out, int out_size) {
    const float* features = (const float*)d_in[0];   // [128,2,256] f32
    const int*   labels   = (const int*)d_in[1];     // [128,1] i32
    float*       out      = (float*)d_out;           // scalar f32

    gram_kernel<<<513, 256>>>(features);
    main_kernel<<<NN, 256>>>(labels);
    fin_kernel<<<1, 1>>>(out);
}

// round 9
// speedup vs baseline: 1.3307x; 1.3307x over previous
#include <cuda_runtime.h>
#include <math.h>

#define NN 256
#define MM 255

// Scratch (no cudaMalloc allowed)
__device__ float  g_gp[4][NN * NN];   // partial Gram per 64-dim chunk
__device__ float  g_nrm[NN];          // squared norms of stacked rows
__device__ double g_acc;

__device__ __forceinline__ float tanha(float x) {
    float y;
    asm("tanh.approx.f32 %0, %1;" : "=f"(y) : "f"(x));
    return y;
}

// ---------------------------------------------------------------------------
// Kernel 1: blocks 0..255: partial Gram G_ij over a 64-dim chunk (32x32 tile,
// 2x2 register tiling, K-major smem). Blocks 256..287: squared norms, 8 rows
// per block, one warp per row, single pass (no serial straggler).
// ---------------------------------------------------------------------------
__global__ void gram_kernel(const float* __restrict__ features) {
    __shared__ float As[64 * 34];
    __shared__ float Bs[64 * 34];

    const int bid = blockIdx.x;
    const int tid = threadIdx.x;

    if (bid >= 256) {                       // norms: 32 blocks x 8 rows
        const int w = tid >> 5, lane = tid & 31;
        const int r = ((bid - 256) << 3) + w;
        const float4* row = (const float4*)(features + ((((r & 127) << 1) + (r >> 7)) << 8));
        const float4 a = row[lane];
        const float4 b = row[lane + 32];
        float s = a.x * a.x + a.y * a.y + a.z * a.z + a.w * a.w
                + b.x * b.x + b.y * b.y + b.z * b.z + b.w * b.w;
#pragma unroll
        for (int o = 16; o; o >>= 1) s += __shfl_xor_sync(0xFFFFFFFFu, s, o);
        if (lane == 0) g_nrm[r] = s;
        return;
    }

    const int jt  = (bid & 7) << 5;
    const int it  = ((bid >> 3) & 7) << 5;
    const int ch  = bid >> 6;               // 0..3 (64-dim chunk)

    if (bid == 0 && tid == 0) g_acc = 0.0;

    {   // load 32 rows x 64 dims (2 float4 per thread per matrix), transpose
        const int r   = tid >> 3;           // 0..31 row
        const int c4  = tid & 7;            // float4 slot 0..7 (and +8)
        const int gi  = it + r;
        const int gj  = jt + r;
        const float* fa = &features[(((gi & 127) << 1) + (gi >> 7)) * 256 + (ch << 6)];
        const float* fb = &features[(((gj & 127) << 1) + (gj >> 7)) * 256 + (ch << 6)];
#pragma unroll
        for (int h = 0; h < 2; h++) {
            const int k0 = ((c4 + (h << 3)) << 2);
            const float4 a = *(const float4*)&fa[k0];
            const float4 b = *(const float4*)&fb[k0];
            As[(k0 + 0) * 34 + r] = a.x;  As[(k0 + 1) * 34 + r] = a.y;
            As[(k0 + 2) * 34 + r] = a.z;  As[(k0 + 3) * 34 + r] = a.w;
            Bs[(k0 + 0) * 34 + r] = b.x;  Bs[(k0 + 1) * 34 + r] = b.y;
            Bs[(k0 + 2) * 34 + r] = b.z;  Bs[(k0 + 3) * 34 + r] = b.w;
        }
    }
    __syncthreads();

    const int ty = tid >> 4;
    const int tx = tid & 15;
    float a00 = 0, a01 = 0, a10 = 0, a11 = 0;
#pragma unroll
    for (int k = 0; k < 64; k++) {
        const float2 a = *(const float2*)&As[k * 34 + (ty << 1)];
        const float2 b = *(const float2*)&Bs[k * 34 + (tx << 1)];
        a00 = fmaf(a.x, b.x, a00);
        a01 = fmaf(a.x, b.y, a01);
        a10 = fmaf(a.y, b.x, a10);
        a11 = fmaf(a.y, b.y, a11);
    }
    const int r0 = it + (ty << 1);
    const int c0 = jt + (tx << 1);
    *(float2*)&g_gp[ch][r0 * NN + c0]       = make_float2(a00, a01);
    *(float2*)&g_gp[ch][(r0 + 1) * NN + c0] = make_float2(a10, a11);
}

// ---------------------------------------------------------------------------
// Kernel 2: 256 blocks (one per row i) x 256 threads.
// Prologue (1 j per thread, all-coalesced loads): z from Gram + norms;
// stable ranks via match_any; records permuted into [+ by lad | - by lad | 0]
// segments. Main loop per permuted k: THREE UNIFORM-BOUND loops over all
// segments, then a small near-warp-uniform fixup that SUBTRACTS the eq-run
// neg terms (recomputed bit-identically) and adds the pos terms. j==k cancels
// the same way; its exact neg value 1 is the accumulator init.
//   + seg:  emd = E_j*e^{zk},  tn = tanh(q_j - ckP), ckP = rhk - zk/2
//   - seg:  emd = E_j*e^{-zk}, tn = tanh(q_j - ckM), ckM = rhk + zk/2
//   0 seg:  neg += 1 + tanh(q_j - rhk)            (q_j = rh_j, d == 0)
//   pos:    ad = |u_j -+ zk|; pos += ad*(1 + tanh(ad/2 - 0.05))
// ---------------------------------------------------------------------------
__global__ void main_kernel(const int* __restrict__ labels) {
    __shared__ float2 sEQ[NN];     // permuted {E_j, q_j = rh_j - u_j/2}
    __shared__ float4 sKR[NN];     // permuted {z, rh, ladf, 0}
    __shared__ float  sU[NN];      // permuted u_j
    __shared__ int    cntL[8][16], cntK[8][32];
    __shared__ int    sumL[16], sumK[32];
    __shared__ int    histBase[16];
    __shared__ int    BP[10], CP[10], BM[10], CM[10];
    __shared__ int    sNP, sNE;
    __shared__ float  red[256];

    const int i    = blockIdx.x;
    const int tid  = threadIdx.x;
    const int lane = tid & 31;
    const int wid  = tid >> 5;
    const unsigned lt = (1u << lane) - 1u;
    const int li   = labels[i & 127];

    cntK[wid][lane] = 0;
    if (tid < 128) cntL[tid >> 4][tid & 15] = 0;
    __syncthreads();

    // ---- phase 1: per-j basics (j = tid), all loads coalesced ----
    float z = 0.0f, sgn = 0.0f;
    int lad = 15, key = 31;
    if (tid < MM) {
        const int c = tid + (tid >= i);
        float gij = 0.0f;
#pragma unroll
        for (int ch = 0; ch < 4; ch++) gij += g_gp[ch][i * NN + c];
        z = sqrtf(fmaxf(fmaf(-2.0f, gij, g_nrm[i] + g_nrm[c]), 0.0f));
        const int ld = li - labels[c & 127];
        lad = ld < 0 ? -ld : ld;
        key = (lad == 0) ? 0 : (ld > 0 ? lad : 16 + lad);
        sgn = (float)((ld > 0) - (ld < 0));
    }
    const unsigned mL = __match_any_sync(0xFFFFFFFFu, lad);
    const unsigned mK = __match_any_sync(0xFFFFFFFFu, key);
    const int tieL = __popc(mL & lt);
    const int tieK = __popc(mK & lt);
    cntL[wid][lad & 15] = __popc(mL);
    cntK[wid][key]      = __popc(mK);
    __syncthreads();

    if (tid < 16) { int s = 0;
#pragma unroll
        for (int g = 0; g < 8; g++) s += cntL[g][tid];
        sumL[tid] = s; }
    if (tid >= 32 && tid < 64) { int s = 0; const int b = tid - 32;
#pragma unroll
        for (int g = 0; g < 8; g++) s += cntK[g][b];
        sumK[b] = s; }
    __syncthreads();

    if (tid == 0) {
        int run = 0;
#pragma unroll
        for (int b = 0; b < 16; b++) { histBase[b] = run; run += sumL[b]; }
        run = 0;
#pragma unroll
        for (int b = 1; b <= 9; b++) { BP[b] = run; CP[b] = sumK[b]; run += sumK[b]; }
        sNP = run;
#pragma unroll
        for (int b = 1; b <= 9; b++) { BM[b] = run; CM[b] = sumK[16 + b]; run += sumK[16 + b]; }
        sNE = run;
        BP[0] = 0; CP[0] = 0; BM[0] = sNP; CM[0] = 0;
    }
    __syncthreads();

    // ---- phase 2: ranks + deterministic placement ----
    if (tid < MM) {
        int tl = tieL, tk = tieK;
        for (int gg = 0; gg < wid; gg++) { tl += cntL[gg][lad]; tk += cntK[gg][key]; }
        const int rank = histBase[lad] + tl;
        const float rh = 5.0f * (float)rank;     // (rank/delta)/2
        int place;
        if (key == 0)       place = sNE + tk;
        else if (key < 16)  place = BP[key] + tk;
        else                place = BM[key - 16] + tk;
        const float u = sgn * z;
        const float E = __expf(-u);
        sEQ[place] = make_float2(E, fmaf(-0.5f, u, rh));
        sKR[place] = make_float4(z, rh, (float)lad, 0.0f);
        sU[place]  = u;
    }
    __syncthreads();

    // ---- main loop: thread handles permuted k position p = tid ----
    float term = 0.0f;
    if (tid < MM) {
        const float4 kr = sKR[tid];
        const float zk  = kr.x;
        const float rhk = kr.y;
        const int ladk  = (int)kr.z;
        const float epk = __expf(zk);
        const float enk = __expf(-zk);
        const float ckP = fmaf(-0.5f, zk, rhk);
        const float ckM = fmaf( 0.5f, zk, rhk);
        const int NP = sNP, NE = sNE;

        float neg = 1.0f;                   // exact j==k contribution
        float pos = 0.0f;

#pragma unroll 4
        for (int j = 0; j < NP; j++) {      // + segment (uniform bounds)
            const float2 t = sEQ[j];
            const float emd = t.x * epk;
            const float tn  = tanha(t.y - ckP);
            neg += fmaf(emd, tn, emd);
        }
#pragma unroll 4
        for (int j = NP; j < NE; j++) {     // - segment (uniform bounds)
            const float2 t = sEQ[j];
            const float emd = t.x * enk;
            const float tn  = tanha(t.y - ckM);
            neg += fmaf(emd, tn, emd);
        }
#pragma unroll 4
        for (int j = NE; j < MM; j++) {     // zero segment (uniform bounds)
            const float tn = tanha(sEQ[j].y - rhk);
            neg += 1.0f + tn;
        }

        // ---- fixup: subtract eq-run neg terms (bit-identical), add pos ----
        if (ladk != 0) {
            const int loP = BP[ladk], hiP = loP + CP[ladk];
            for (int j = loP; j < hiP; j++) {
                const float2 t = sEQ[j];
                const float emd = t.x * epk;
                const float tn  = tanha(t.y - ckP);
                neg -= fmaf(emd, tn, emd);
                const float d  = sU[j] - zk;
                const float ad = fabsf(d);
                pos += fmaf(ad, tanha(fmaf(0.5f, ad, -0.05f)), ad);
            }
            const int loM = BM[ladk], hiM = loM + CM[ladk];
            for (int j = loM; j < hiM; j++) {
                const float2 t = sEQ[j];
                const float emd = t.x * enk;
                const float tn  = tanha(t.y - ckM);
                neg -= fmaf(emd, tn, emd);
                const float d  = sU[j] + zk;
                const float ad = fabsf(d);
                pos += fmaf(ad, tanha(fmaf(0.5f, ad, -0.05f)), ad);
            }
        } else {
            for (int j = NE; j < MM; j++) { // zero-seg pairs are pos (== 0)
                const float tn = tanha(sEQ[j].y - rhk);
                neg -= 1.0f + tn;           // includes j==k's exact 1; init restores it
            }
        }
        term = pos + logf(neg);
    }
    red[tid] = term;
    __syncthreads();
#pragma unroll
    for (int s = 128; s > 0; s >>= 1) {
        if (tid < s) red[tid] += red[tid + s];
        __syncthreads();
    }
    if (tid == 0) atomicAdd(&g_acc, (double)red[0]);
}

__global__ void fin_kernel(float* __restrict__ out) {
    out[0] = (float)(g_acc / (double)(NN * MM));
}

extern "C" void kernel_launch(void* const* d_in, const int* in_sizes, int n_in,
                              void* d_out, int out_size) {
    const float* features = (const float*)d_in[0];   // [128,2,256] f32
    const int*   labels   = (const int*)d_in[1];     // [128,1] i32
    float*       out      = (float*)d_out;           // scalar f32

    gram_kernel<<<288, 256>>>(features);
    main_kernel<<<NN, 256>>>(labels);
    fin_kernel<<<1, 1>>>(out);
}